// round 13
// baseline (speedup 1.0000x reference)
#include <cuda_runtime.h>
#include <cstdint>

// Problem constants
#define B  4
#define C  64
#define H  256
#define W  256
#define HW (H*W)              // 65536
#define NPIX (B*HW)           // 262144 source pixels
#define NIMG (C*HW)           // 4194304 image elements

#define RGRID 1024            // reduce grid: 1024*256 threads * 4 float4 = NIMG

// Scratch image as float4 per (group, y, x): img4[g*HW + y*W + x] holds
// channels {4g..4g+3} of pixel (y,x).
// __device__ globals are zero-initialized at load; the reduce re-zeroes
// everything it consumes, so every kernel_launch call sees clean state.
__device__ float4       g_image4[NIMG / 4];   // 16 MB
__device__ double       g_acc[2];             // [0]=sum, [1]=sumsq
__device__ unsigned int g_count;              // reduce block completion counter

// 8B vector RED (channel pair within a float4 cell; offsets 0/8 are 8B-aligned)
__device__ __forceinline__ void red2(float* ptr, float a, float b) {
    asm volatile("red.global.add.v2.f32 [%0], {%1,%2};"
                 :: "l"(ptr), "f"(a), "f"(b) : "memory");
}

// ---------------------------------------------------------------------------
// Per-pixel deposit of one 4-channel group (R8-proven hierarchy).
// ---------------------------------------------------------------------------
__device__ __forceinline__ void deposit_one(
    float4* plane, bool unif,
    const int* x0, const int* y0,
    const float* w00, const float* w10, const float* w01, const float* w11)
{
    if (unif) {
        const int X0 = x0[0], Y0 = y0[0];
        const bool vx0 = (X0 >= 0)  & (X0 < W);
        const bool vx1 = (X0 >= -1) & (X0 < W - 1);
        if (Y0 >= 0 && Y0 < H) {
            float4* row = plane + Y0 * W;
            if (vx0) atomicAdd(row + X0,     make_float4(w00[0], w00[1], w00[2], w00[3]));
            if (vx1) atomicAdd(row + X0 + 1, make_float4(w10[0], w10[1], w10[2], w10[3]));
        }
        if (Y0 >= -1 && Y0 < H - 1) {
            float4* row = plane + (Y0 + 1) * W;
            if (vx0) atomicAdd(row + X0,     make_float4(w01[0], w01[1], w01[2], w01[3]));
            if (vx1) atomicAdd(row + X0 + 1, make_float4(w11[0], w11[1], w11[2], w11[3]));
        }
        return;
    }
    // straddle: channel pairs {0,1} and {2,3}
    float* pf = reinterpret_cast<float*>(plane);
    #pragma unroll
    for (int h = 0; h < 2; ++h) {
        const int k0 = 2 * h;
        const int k1 = k0 + 1;
        if ((x0[k0] == x0[k1]) & (y0[k0] == y0[k1])) {
            const int X0 = x0[k0], Y0 = y0[k0];
            const bool vx0 = (X0 >= 0)  & (X0 < W);
            const bool vx1 = (X0 >= -1) & (X0 < W - 1);
            if (Y0 >= 0 && Y0 < H) {
                float* row = pf + (size_t)(Y0 * W) * 4 + k0;
                if (vx0) red2(row + (size_t)X0 * 4,       w00[k0], w00[k1]);
                if (vx1) red2(row + (size_t)(X0 + 1) * 4, w10[k0], w10[k1]);
            }
            if (Y0 >= -1 && Y0 < H - 1) {
                float* row = pf + (size_t)((Y0 + 1) * W) * 4 + k0;
                if (vx0) red2(row + (size_t)X0 * 4,       w01[k0], w01[k1]);
                if (vx1) red2(row + (size_t)(X0 + 1) * 4, w11[k0], w11[k1]);
            }
        } else {
            #pragma unroll
            for (int k = k0; k <= k1; ++k) {
                const int X0 = x0[k], Y0 = y0[k];
                const bool vx0 = (X0 >= 0)  & (X0 < W);
                const bool vx1 = (X0 >= -1) & (X0 < W - 1);
                if (Y0 >= 0 && Y0 < H) {
                    float* row = pf + (size_t)(Y0 * W) * 4 + k;
                    if (vx0) atomicAdd(row + (size_t)X0 * 4,       w00[k]);
                    if (vx1) atomicAdd(row + (size_t)(X0 + 1) * 4, w10[k]);
                }
                if (Y0 >= -1 && Y0 < H - 1) {
                    float* row = pf + (size_t)((Y0 + 1) * W) * 4 + k;
                    if (vx0) atomicAdd(row + (size_t)X0 * 4,       w01[k]);
                    if (vx1) atomicAdd(row + (size_t)(X0 + 1) * 4, w11[k]);
                }
            }
        }
    }
}

// ---------------------------------------------------------------------------
// Kernel 1: forward bilinear splat, one thread per x-adjacent PIXEL PAIR.
// When both pixels' 4-channel groups are cell-uniform and row-aligned:
//   x-shift 1 -> merged 2x3 footprint: 6 REDs (24 adds) instead of 8 (32)
//   x-shift 0 -> identical cells:      4 REDs (16 adds) instead of 8 (32)
// Middle-column weights merged in registers (exact fp32 adds).
// ---------------------------------------------------------------------------
__global__ void __launch_bounds__(256) splat_kernel(
    const float* __restrict__ flow,
    const float* __restrict__ spike)
{
    const int t  = blockIdx.x * blockDim.x + threadIdx.x;  // pair index
    const int b  = t >> 15;            // 32768 pairs per batch
    const int p2 = t & 32767;
    const int y  = p2 >> 7;            // 128 pairs per row
    const int xA = (p2 & 127) << 1;    // even column
    const int p  = (y << 8) | xA;      // pixel A linear index

    const float uA = flow[(size_t)b * 2 * HW + p];
    const float vA = flow[(size_t)b * 2 * HW + HW + p];
    const float uB = flow[(size_t)b * 2 * HW + p + 1];
    const float vB = flow[(size_t)b * 2 * HW + HW + p + 1];
    const float* spA = spike + (size_t)b * C * HW + p;

    const float xfA = (float)xA;
    const float xfB = (float)(xA + 1);
    const float yf  = (float)y;

    #pragma unroll 1
    for (int g = 0; g < C / 4; ++g) {
        float wA00[4], wA10[4], wA01[4], wA11[4];
        float wB00[4], wB10[4], wB01[4], wB11[4];
        int   xa[4], ya[4], xb[4], yb[4];

        #pragma unroll
        for (int k = 0; k < 4; ++k) {
            const int c = g * 4 + k;
            const float s = ((float)c - 31.5f) * (1.0f / 64.0f);
            const float* sc = spA + (size_t)c * HW;
            // pixel A
            {
                const float val = __ldg(sc);
                const float xn = fmaf(uA, s, xfA);
                const float yn = fmaf(vA, s, yf);
                const float fx = floorf(xn);
                const float fy = floorf(yn);
                const float wx = xn - fx, wy = yn - fy;
                xa[k] = (int)fx; ya[k] = (int)fy;
                const float a  = val * wx;
                const float bb = val - a;
                const float q  = 1.0f - wy;
                wA00[k] = bb * q;  wA10[k] = a * q;
                wA01[k] = bb * wy; wA11[k] = a * wy;
            }
            // pixel B
            {
                const float val = __ldg(sc + 1);
                const float xn = fmaf(uB, s, xfB);
                const float yn = fmaf(vB, s, yf);
                const float fx = floorf(xn);
                const float fy = floorf(yn);
                const float wx = xn - fx, wy = yn - fy;
                xb[k] = (int)fx; yb[k] = (int)fy;
                const float a  = val * wx;
                const float bb = val - a;
                const float q  = 1.0f - wy;
                wB00[k] = bb * q;  wB10[k] = a * q;
                wB01[k] = bb * wy; wB11[k] = a * wy;
            }
        }

        const bool unifA = (xa[0] == xa[3]) & (ya[0] == ya[3]);
        const bool unifB = (xb[0] == xb[3]) & (yb[0] == yb[3]);
        float4* plane = g_image4 + (size_t)g * HW;

        const int d = xb[0] - xa[0];
        if (unifA & unifB & (ya[0] == yb[0]) & ((d == 1) | (d == 0))) {
            const int X = xa[0], Y = ya[0];
            if (d == 1) {
                // merged 2x3 footprint: cols X, X+1, X+2; rows Y, Y+1
                float4 c0t, c1t, c2t, c0b, c1b, c2b;
                {
                    c0t = make_float4(wA00[0], wA00[1], wA00[2], wA00[3]);
                    c1t = make_float4(wA10[0] + wB00[0], wA10[1] + wB00[1],
                                      wA10[2] + wB00[2], wA10[3] + wB00[3]);
                    c2t = make_float4(wB10[0], wB10[1], wB10[2], wB10[3]);
                    c0b = make_float4(wA01[0], wA01[1], wA01[2], wA01[3]);
                    c1b = make_float4(wA11[0] + wB01[0], wA11[1] + wB01[1],
                                      wA11[2] + wB01[2], wA11[3] + wB01[3]);
                    c2b = make_float4(wB11[0], wB11[1], wB11[2], wB11[3]);
                }
                const bool v0 = (X >= 0)  & (X < W);
                const bool v1 = (X >= -1) & (X < W - 1);
                const bool v2 = (X >= -2) & (X < W - 2);
                if (Y >= 0 && Y < H) {
                    float4* row = plane + Y * W;
                    if (v0) atomicAdd(row + X,     c0t);
                    if (v1) atomicAdd(row + X + 1, c1t);
                    if (v2) atomicAdd(row + X + 2, c2t);
                }
                if (Y >= -1 && Y < H - 1) {
                    float4* row = plane + (Y + 1) * W;
                    if (v0) atomicAdd(row + X,     c0b);
                    if (v1) atomicAdd(row + X + 1, c1b);
                    if (v2) atomicAdd(row + X + 2, c2b);
                }
            } else {
                // identical cells: 4 merged REDs
                float4 m00 = make_float4(wA00[0] + wB00[0], wA00[1] + wB00[1],
                                         wA00[2] + wB00[2], wA00[3] + wB00[3]);
                float4 m10 = make_float4(wA10[0] + wB10[0], wA10[1] + wB10[1],
                                         wA10[2] + wB10[2], wA10[3] + wB10[3]);
                float4 m01 = make_float4(wA01[0] + wB01[0], wA01[1] + wB01[1],
                                         wA01[2] + wB01[2], wA01[3] + wB01[3]);
                float4 m11 = make_float4(wA11[0] + wB11[0], wA11[1] + wB11[1],
                                         wA11[2] + wB11[2], wA11[3] + wB11[3]);
                const bool v0 = (X >= 0)  & (X < W);
                const bool v1 = (X >= -1) & (X < W - 1);
                if (Y >= 0 && Y < H) {
                    float4* row = plane + Y * W;
                    if (v0) atomicAdd(row + X,     m00);
                    if (v1) atomicAdd(row + X + 1, m10);
                }
                if (Y >= -1 && Y < H - 1) {
                    float4* row = plane + (Y + 1) * W;
                    if (v0) atomicAdd(row + X,     m01);
                    if (v1) atomicAdd(row + X + 1, m11);
                }
            }
        } else {
            deposit_one(plane, unifA, xa, ya, wA00, wA10, wA01, wA11);
            deposit_one(plane, unifB, xb, yb, wB00, wB10, wB01, wB11);
        }
    }
}

// ---------------------------------------------------------------------------
// Kernel 2: fused reduce + finalize (unchanged, proven).
// ---------------------------------------------------------------------------
__global__ void __launch_bounds__(256) reduce_final_kernel(float* __restrict__ out) {
    const int lane = threadIdx.x & 31;
    const int gwarp = (blockIdx.x * 256 + threadIdx.x) >> 5;
    const int base = gwarp * 128 + lane;          // float4 index

    const float4 v0 = g_image4[base];
    const float4 v1 = g_image4[base + 32];
    const float4 v2 = g_image4[base + 64];
    const float4 v3 = g_image4[base + 96];

    const float4 z4 = make_float4(0.f, 0.f, 0.f, 0.f);
    g_image4[base]      = z4;                     // re-zero for next replay
    g_image4[base + 32] = z4;
    g_image4[base + 64] = z4;
    g_image4[base + 96] = z4;

    float fs  = ((v0.x + v0.y) + (v0.z + v0.w)) + ((v1.x + v1.y) + (v1.z + v1.w))
              + ((v2.x + v2.y) + (v2.z + v2.w)) + ((v3.x + v3.y) + (v3.z + v3.w));
    float fs2 = (fmaf(v0.x, v0.x, v0.y * v0.y) + fmaf(v0.z, v0.z, v0.w * v0.w))
              + (fmaf(v1.x, v1.x, v1.y * v1.y) + fmaf(v1.z, v1.z, v1.w * v1.w))
              + (fmaf(v2.x, v2.x, v2.y * v2.y) + fmaf(v2.z, v2.z, v2.w * v2.w))
              + (fmaf(v3.x, v3.x, v3.y * v3.y) + fmaf(v3.z, v3.z, v3.w * v3.w));

    double s  = (double)fs;
    double s2 = (double)fs2;

    #pragma unroll
    for (int o = 16; o > 0; o >>= 1) {
        s  += __shfl_down_sync(0xFFFFFFFFu, s,  o);
        s2 += __shfl_down_sync(0xFFFFFFFFu, s2, o);
    }
    __shared__ double sh[2][8];
    const int wid = threadIdx.x >> 5;
    if (lane == 0) { sh[0][wid] = s; sh[1][wid] = s2; }
    __syncthreads();

    __shared__ bool is_last;
    if (threadIdx.x == 0) {
        double bs = 0.0, bs2 = 0.0;
        #pragma unroll
        for (int w = 0; w < 8; ++w) { bs += sh[0][w]; bs2 += sh[1][w]; }
        atomicAdd(&g_acc[0], bs);
        atomicAdd(&g_acc[1], bs2);
        __threadfence();
        unsigned int t = atomicAdd(&g_count, 1u);
        is_last = (t == RGRID - 1);
    }
    __syncthreads();

    if (is_last && threadIdx.x == 0) {
        const double sum   = g_acc[0];
        const double sumsq = g_acc[1];
        const double Nd    = (double)NIMG;
        const double var   = (sumsq - sum * sum / Nd) / (Nd - 1.0);
        out[0] = (float)(-var);
        // reset for next replay
        g_acc[0] = 0.0;
        g_acc[1] = 0.0;
        g_count  = 0u;
    }
}

// ---------------------------------------------------------------------------
extern "C" void kernel_launch(void* const* d_in, const int* in_sizes, int n_in,
                              void* d_out, int out_size)
{
    const float* flow;
    const float* spike;
    if (in_sizes[0] == 2 * NPIX) {
        flow  = (const float*)d_in[0];
        spike = (const float*)d_in[1];
    } else {
        flow  = (const float*)d_in[1];
        spike = (const float*)d_in[0];
    }
    float* out = (float*)d_out;

    splat_kernel<<<NPIX / 2 / 256, 256>>>(flow, spike);   // 512 CTAs, one thread per pixel pair
    reduce_final_kernel<<<RGRID, 256>>>(out);
}

// round 14
// speedup vs baseline: 1.3157x; 1.3157x over previous
#include <cuda_runtime.h>
#include <cstdint>

// Problem constants
#define B  4
#define C  64
#define H  256
#define W  256
#define HW (H*W)              // 65536
#define NPIX (B*HW)           // 262144 source pixels
#define NIMG (C*HW)           // 4194304 image elements

#define SBLOCK 128            // splat block size (finer CTA granularity)
#define RGRID 1024            // reduce grid: 1024*256 threads * 4 float4 = NIMG

// Scratch image as float4 per (group, y, x): img4[g*HW + y*W + x] holds
// channels {4g..4g+3} of pixel (y,x). Warp lanes are consecutive x, so a
// warp's 32 float4 REDs to one corner land in few contiguous cache lines.
// __device__ globals are zero-initialized at load; the reduce re-zeroes
// everything it consumes, so every kernel_launch call sees clean state.
__device__ float4       g_image4[NIMG / 4];   // 16 MB
__device__ double       g_acc[2];             // [0]=sum, [1]=sumsq
__device__ unsigned int g_count;              // reduce block completion counter

// 8B vector RED (channel pair within a float4 cell; offsets 0/8 are 8B-aligned)
__device__ __forceinline__ void red2(float* ptr, float a, float b) {
    asm volatile("red.global.add.v2.f32 [%0], {%1,%2};"
                 :: "l"(ptr), "f"(a), "f"(b) : "memory");
}

// ---------------------------------------------------------------------------
// Kernel 1: forward bilinear splat, 4 channels per float4 RED.
// One thread per source pixel; 16 groups of 4 channels. Displacement u*s_c is
// monotone in c -> endpoint channels decide whether the whole 4-group shares
// one corner cell (~93%) -> 4 float4 REDs. Straddle: uniform channel pairs
// via v2 REDs, else scalar. This sits at the REDG issue-rate floor
// (16.8M lane-REDs x 1.29 cyc / 148 SMs ~ 81us).
// ---------------------------------------------------------------------------
__global__ void __launch_bounds__(SBLOCK) splat_kernel(
    const float* __restrict__ flow,
    const float* __restrict__ spike)
{
    const int idx = blockIdx.x * blockDim.x + threadIdx.x;   // grid exact

    const int b = idx >> 16;          // / HW
    const int p = idx & (HW - 1);     // % HW
    const int y = p >> 8;             // / W
    const int x = p & (W - 1);        // % W

    const float u = flow[(size_t)b * 2 * HW + p];
    const float v = flow[(size_t)b * 2 * HW + HW + p];
    const float* sp = spike + (size_t)b * C * HW + p;

    const float xf = (float)x;
    const float yf = (float)y;

    #pragma unroll
    for (int g = 0; g < C / 4; ++g) {
        float val[4], wx[4], wy[4];
        int   x0[4], y0[4];

        #pragma unroll
        for (int k = 0; k < 4; ++k) {
            const int c = g * 4 + k;
            val[k] = __ldg(sp + (size_t)c * HW);
            const float s  = ((float)c - 31.5f) * (1.0f / 64.0f);
            const float xn = fmaf(u, s, xf);
            const float yn = fmaf(v, s, yf);
            const float fx = floorf(xn);
            const float fy = floorf(yn);
            wx[k] = xn - fx;
            wy[k] = yn - fy;
            x0[k] = (int)fx;
            y0[k] = (int)fy;
        }

        float4* plane = g_image4 + (size_t)g * HW;

        if ((x0[0] == x0[3]) & (y0[0] == y0[3])) {
            // ---- fast path: whole group shares one corner cell ----
            const int X0 = x0[0], Y0 = y0[0];

            float4 w00, w10, w01, w11;
            {
                float a0 = val[0] * wx[0], b0 = val[0] - a0;   // a=val*wx, b=val*(1-wx)
                float a1 = val[1] * wx[1], b1 = val[1] - a1;
                float a2 = val[2] * wx[2], b2 = val[2] - a2;
                float a3 = val[3] * wx[3], b3 = val[3] - a3;
                float q0 = 1.0f - wy[0], q1 = 1.0f - wy[1];
                float q2 = 1.0f - wy[2], q3 = 1.0f - wy[3];
                w00 = make_float4(b0*q0,    b1*q1,    b2*q2,    b3*q3);
                w10 = make_float4(a0*q0,    a1*q1,    a2*q2,    a3*q3);
                w01 = make_float4(b0*wy[0], b1*wy[1], b2*wy[2], b3*wy[3]);
                w11 = make_float4(a0*wy[0], a1*wy[1], a2*wy[2], a3*wy[3]);
            }

            const bool vx0 = (X0 >= 0)  & (X0 < W);
            const bool vx1 = (X0 >= -1) & (X0 < W - 1);

            if (Y0 >= 0 && Y0 < H) {
                float4* row = plane + Y0 * W;
                if (vx0) atomicAdd(row + X0,     w00);
                if (vx1) atomicAdd(row + X0 + 1, w10);
            }
            if (Y0 >= -1 && Y0 < H - 1) {
                float4* row = plane + (Y0 + 1) * W;
                if (vx0) atomicAdd(row + X0,     w01);
                if (vx1) atomicAdd(row + X0 + 1, w11);
            }
        } else {
            // ---- straddle: handle channel pairs {0,1} and {2,3} ----
            float* pf = reinterpret_cast<float*>(plane);

            #pragma unroll
            for (int h = 0; h < 2; ++h) {
                const int k0 = 2 * h;
                const int k1 = k0 + 1;

                if ((x0[k0] == x0[k1]) & (y0[k0] == y0[k1])) {
                    const int X0 = x0[k0], Y0 = y0[k0];
                    const float a0 = val[k0] * wx[k0], b0 = val[k0] - a0;
                    const float a1 = val[k1] * wx[k1], b1 = val[k1] - a1;
                    const float q0 = 1.0f - wy[k0], q1 = 1.0f - wy[k1];

                    const bool vx0 = (X0 >= 0)  & (X0 < W);
                    const bool vx1 = (X0 >= -1) & (X0 < W - 1);

                    if (Y0 >= 0 && Y0 < H) {
                        float* row = pf + (size_t)(Y0 * W) * 4 + k0;
                        if (vx0) red2(row + (size_t)X0 * 4,       b0 * q0, b1 * q1);
                        if (vx1) red2(row + (size_t)(X0 + 1) * 4, a0 * q0, a1 * q1);
                    }
                    if (Y0 >= -1 && Y0 < H - 1) {
                        float* row = pf + (size_t)((Y0 + 1) * W) * 4 + k0;
                        if (vx0) red2(row + (size_t)X0 * 4,       b0 * wy[k0], b1 * wy[k1]);
                        if (vx1) red2(row + (size_t)(X0 + 1) * 4, a0 * wy[k0], a1 * wy[k1]);
                    }
                } else {
                    #pragma unroll
                    for (int k = k0; k <= k1; ++k) {
                        const int X0 = x0[k], Y0 = y0[k];
                        const float a  = val[k] * wx[k];
                        const float bb = val[k] - a;
                        const float q  = 1.0f - wy[k];

                        const bool vx0 = (X0 >= 0)  & (X0 < W);
                        const bool vx1 = (X0 >= -1) & (X0 < W - 1);

                        if (Y0 >= 0 && Y0 < H) {
                            float* row = pf + (size_t)(Y0 * W) * 4 + k;
                            if (vx0) atomicAdd(row + (size_t)X0 * 4,       bb * q);
                            if (vx1) atomicAdd(row + (size_t)(X0 + 1) * 4, a  * q);
                        }
                        if (Y0 >= -1 && Y0 < H - 1) {
                            float* row = pf + (size_t)((Y0 + 1) * W) * 4 + k;
                            if (vx0) atomicAdd(row + (size_t)X0 * 4,       bb * wy[k]);
                            if (vx1) atomicAdd(row + (size_t)(X0 + 1) * 4, a  * wy[k]);
                        }
                    }
                }
            }
        }
    }
}

// ---------------------------------------------------------------------------
// Kernel 2: fused reduce + finalize.
// Each warp owns 4 consecutive 512B chunks; 4 independent coalesced float4
// loads per thread (MLP=4). fp32 partials (16 values/thread, O(1) magnitude)
// promoted to double at warp level. Re-zeroes the image for the next graph
// replay; globally-last block computes -var(ddof=1).
// ---------------------------------------------------------------------------
__global__ void __launch_bounds__(256) reduce_final_kernel(float* __restrict__ out) {
    const int lane = threadIdx.x & 31;
    const int gwarp = (blockIdx.x * 256 + threadIdx.x) >> 5;
    const int base = gwarp * 128 + lane;          // float4 index

    const float4 v0 = g_image4[base];
    const float4 v1 = g_image4[base + 32];
    const float4 v2 = g_image4[base + 64];
    const float4 v3 = g_image4[base + 96];

    const float4 z4 = make_float4(0.f, 0.f, 0.f, 0.f);
    g_image4[base]      = z4;                     // re-zero for next replay
    g_image4[base + 32] = z4;
    g_image4[base + 64] = z4;
    g_image4[base + 96] = z4;

    float fs  = ((v0.x + v0.y) + (v0.z + v0.w)) + ((v1.x + v1.y) + (v1.z + v1.w))
              + ((v2.x + v2.y) + (v2.z + v2.w)) + ((v3.x + v3.y) + (v3.z + v3.w));
    float fs2 = (fmaf(v0.x, v0.x, v0.y * v0.y) + fmaf(v0.z, v0.z, v0.w * v0.w))
              + (fmaf(v1.x, v1.x, v1.y * v1.y) + fmaf(v1.z, v1.z, v1.w * v1.w))
              + (fmaf(v2.x, v2.x, v2.y * v2.y) + fmaf(v2.z, v2.z, v2.w * v2.w))
              + (fmaf(v3.x, v3.x, v3.y * v3.y) + fmaf(v3.z, v3.z, v3.w * v3.w));

    double s  = (double)fs;
    double s2 = (double)fs2;

    #pragma unroll
    for (int o = 16; o > 0; o >>= 1) {
        s  += __shfl_down_sync(0xFFFFFFFFu, s,  o);
        s2 += __shfl_down_sync(0xFFFFFFFFu, s2, o);
    }
    __shared__ double sh[2][8];
    const int wid = threadIdx.x >> 5;
    if (lane == 0) { sh[0][wid] = s; sh[1][wid] = s2; }
    __syncthreads();

    __shared__ bool is_last;
    if (threadIdx.x == 0) {
        double bs = 0.0, bs2 = 0.0;
        #pragma unroll
        for (int w = 0; w < 8; ++w) { bs += sh[0][w]; bs2 += sh[1][w]; }
        atomicAdd(&g_acc[0], bs);
        atomicAdd(&g_acc[1], bs2);
        __threadfence();
        unsigned int t = atomicAdd(&g_count, 1u);
        is_last = (t == RGRID - 1);
    }
    __syncthreads();

    if (is_last && threadIdx.x == 0) {
        const double sum   = g_acc[0];
        const double sumsq = g_acc[1];
        const double Nd    = (double)NIMG;
        const double var   = (sumsq - sum * sum / Nd) / (Nd - 1.0);
        out[0] = (float)(-var);
        // reset for next replay
        g_acc[0] = 0.0;
        g_acc[1] = 0.0;
        g_count  = 0u;
    }
}

// ---------------------------------------------------------------------------
extern "C" void kernel_launch(void* const* d_in, const int* in_sizes, int n_in,
                              void* d_out, int out_size)
{
    const float* flow;
    const float* spike;
    if (in_sizes[0] == 2 * NPIX) {
        flow  = (const float*)d_in[0];
        spike = (const float*)d_in[1];
    } else {
        flow  = (const float*)d_in[1];
        spike = (const float*)d_in[0];
    }
    float* out = (float*)d_out;

    splat_kernel<<<NPIX / SBLOCK, SBLOCK>>>(flow, spike);
    reduce_final_kernel<<<RGRID, 256>>>(out);
}